// round 15
// baseline (speedup 1.0000x reference)
#include <cuda_runtime.h>
#include <cuda_bf16.h>
#include <cstdint>
#include <cstddef>

#define NN 16384
#define EE 524288
#define NF 256
#define NH 128

// ---------------- scratch (static device globals; no runtime alloc) ----------------
__device__ float g_t [NN * NH];
__device__ float g_b1[NN * NH];
__device__ float g_b2[NN * NH];
__device__ __nv_bfloat16 g_sb[NN * NH];
__device__ int   g_deg[NN];
__device__ int   g_rowptr[NN + 1];
__device__ int   g_cursor[NN];
__device__ int   g_col[EE];
__device__ float g_dinv[NN];
__device__ int   g_idx64;

// ---------------- helpers ----------------
__device__ __forceinline__ uint32_t smem_u32(const void* p) {
    uint32_t a;
    asm("{ .reg .u64 t; cvta.to.shared.u64 t, %1; cvt.u32.u64 %0, t; }" : "=r"(a) : "l"(p));
    return a;
}
__device__ __forceinline__ void ldmx4(uint32_t* r, uint32_t addr) {
    asm volatile("ldmatrix.sync.aligned.m8n8.x4.shared.b16 {%0,%1,%2,%3}, [%4];"
                 : "=r"(r[0]), "=r"(r[1]), "=r"(r[2]), "=r"(r[3]) : "r"(addr));
}
__device__ __forceinline__ void ldmx4t(uint32_t* r, uint32_t addr) {
    asm volatile("ldmatrix.sync.aligned.m8n8.x4.trans.shared.b16 {%0,%1,%2,%3}, [%4];"
                 : "=r"(r[0]), "=r"(r[1]), "=r"(r[2]), "=r"(r[3]) : "r"(addr));
}
__device__ __forceinline__ void mma16816(float* c, const uint32_t* a,
                                         uint32_t b0, uint32_t b1) {
    asm volatile(
        "mma.sync.aligned.m16n8k16.row.col.f32.bf16.bf16.f32 "
        "{%0,%1,%2,%3}, {%4,%5,%6,%7}, {%8,%9}, {%0,%1,%2,%3};"
        : "+f"(c[0]), "+f"(c[1]), "+f"(c[2]), "+f"(c[3])
        : "r"(a[0]), "r"(a[1]), "r"(a[2]), "r"(a[3]), "r"(b0), "r"(b1));
}
__device__ __forceinline__ void cpa16(uint32_t dst, const void* src) {
    asm volatile("cp.async.cg.shared.global [%0], [%1], 16;" :: "r"(dst), "l"(src));
}
__device__ __forceinline__ void cpa_commit() {
    asm volatile("cp.async.commit_group;" ::: "memory");
}
template <int NPEND>
__device__ __forceinline__ void cpa_wait() {
    asm volatile("cp.async.wait_group %0;" :: "n"(NPEND) : "memory");
}
__device__ __forceinline__ void stg128_cs(float* p, float x, float y, float z, float w) {
    asm volatile("st.global.cs.v4.f32 [%0], {%1,%2,%3,%4};"
                 :: "l"(p), "f"(x), "f"(y), "f"(z), "f"(w) : "memory");
}

// ---------------- preprocessing kernels ----------------
__global__ void detect_k(const int* __restrict__ ei) {
    int t = threadIdx.x;                 // 128 threads
    int v = ei[2 * t + 1];               // high word if int64 layout
    int ok = __syncthreads_and(v == 0);
    if (t == 0) g_idx64 = ok ? 1 : 0;
}
__global__ void zero_k() {
    int i = blockIdx.x * blockDim.x + threadIdx.x;
    if (i < NN) g_deg[i] = 0;
}
__global__ void degree_k(const int* __restrict__ ei) {
    int e = blockIdx.x * blockDim.x + threadIdx.x;
    if (e >= EE) return;
    int d = g_idx64 ? ei[2 * (EE + e)] : ei[EE + e];
    atomicAdd(&g_deg[d], 1);
}
__global__ void dinv_k() {
    int i = blockIdx.x * blockDim.x + threadIdx.x;
    if (i < NN) g_dinv[i] = rsqrtf((float)g_deg[i] + 1.0f);
}
__global__ void scan_k() {
    __shared__ int sums[1024];
    int t = threadIdx.x;
    int base = t * 16;
    int local[16];
    int s = 0;
#pragma unroll
    for (int i = 0; i < 16; i++) { local[i] = s; s += g_deg[base + i]; }
    sums[t] = s;
    __syncthreads();
    for (int off = 1; off < 1024; off <<= 1) {
        int v = (t >= off) ? sums[t - off] : 0;
        __syncthreads();
        sums[t] += v;
        __syncthreads();
    }
    int pre = (t > 0) ? sums[t - 1] : 0;
#pragma unroll
    for (int i = 0; i < 16; i++) g_rowptr[base + i] = pre + local[i];
    if (t == 1023) g_rowptr[NN] = sums[1023];
}
__global__ void copycur_k() {
    int i = blockIdx.x * blockDim.x + threadIdx.x;
    if (i < NN) g_cursor[i] = g_rowptr[i];
}
__global__ void scatter_k(const int* __restrict__ ei) {
    int e = blockIdx.x * blockDim.x + threadIdx.x;
    if (e >= EE) return;
    int s, d;
    if (g_idx64) { s = ei[2 * e]; d = ei[2 * (EE + e)]; }
    else         { s = ei[e];     d = ei[EE + e]; }
    int p = atomicAdd(&g_cursor[d], 1);
    g_col[p] = s;
}

// ---------------- 3xbf16-split tensor GEMM: C[M,N] = A[M,K] @ B[K,N] (+bias, relu) ----
#define GP 136
#define G_AHI 0
#define G_ALO (128 * GP * 2)
#define G_BHI (2 * 128 * GP * 2)
#define G_BLO (3 * 128 * GP * 2)
#define G_SMEM (4 * 128 * GP * 2)

__global__ void __launch_bounds__(256) gemm3bf_k(const float* __restrict__ A,
                                                 const float* __restrict__ B,
                                                 const float* __restrict__ bias,
                                                 float* __restrict__ C,
                                                 int M, int K, int N, int doBiasRelu) {
    extern __shared__ char smem[];
    uint32_t sb = smem_u32(smem);
    int tid = threadIdx.x, lane = tid & 31, wid = tid >> 5;
    int wm = wid & 3, wn = wid >> 2;
    int m0 = blockIdx.x * 128, n0 = blockIdx.y * 128;

    float c[2][8][4];
#pragma unroll
    for (int mt = 0; mt < 2; mt++)
#pragma unroll
        for (int nt = 0; nt < 8; nt++)
#pragma unroll
            for (int q = 0; q < 4; q++) c[mt][nt][q] = 0.0f;

    for (int k0 = 0; k0 < K; k0 += 128) {
#pragma unroll
        for (int i = 0; i < 16; i++) {
            int idx = tid + i * 256;
            int r = idx >> 5, c4 = (idx & 31) << 2;
            float4 v = *(const float4*)(A + (size_t)(m0 + r) * K + k0 + c4);
            __nv_bfloat16 h0 = __float2bfloat16_rn(v.x), h1 = __float2bfloat16_rn(v.y);
            __nv_bfloat16 h2 = __float2bfloat16_rn(v.z), h3 = __float2bfloat16_rn(v.w);
            __nv_bfloat16 l0 = __float2bfloat16_rn(v.x - __bfloat162float(h0));
            __nv_bfloat16 l1 = __float2bfloat16_rn(v.y - __bfloat162float(h1));
            __nv_bfloat16 l2 = __float2bfloat16_rn(v.z - __bfloat162float(h2));
            __nv_bfloat16 l3 = __float2bfloat16_rn(v.w - __bfloat162float(h3));
            uint32_t hA = (uint32_t)__bfloat16_as_ushort(h0) |
                          ((uint32_t)__bfloat16_as_ushort(h1) << 16);
            uint32_t hB = (uint32_t)__bfloat16_as_ushort(h2) |
                          ((uint32_t)__bfloat16_as_ushort(h3) << 16);
            uint32_t lA = (uint32_t)__bfloat16_as_ushort(l0) |
                          ((uint32_t)__bfloat16_as_ushort(l1) << 16);
            uint32_t lB = (uint32_t)__bfloat16_as_ushort(l2) |
                          ((uint32_t)__bfloat16_as_ushort(l3) << 16);
            *(uint2*)(smem + G_AHI + (size_t)(r * GP + c4) * 2) = make_uint2(hA, hB);
            *(uint2*)(smem + G_ALO + (size_t)(r * GP + c4) * 2) = make_uint2(lA, lB);
        }
#pragma unroll
        for (int i = 0; i < 16; i++) {
            int idx = tid + i * 256;
            int r = idx >> 5, c4 = (idx & 31) << 2;
            float4 v = *(const float4*)(B + (size_t)(k0 + r) * N + n0 + c4);
            __nv_bfloat16 h0 = __float2bfloat16_rn(v.x), h1 = __float2bfloat16_rn(v.y);
            __nv_bfloat16 h2 = __float2bfloat16_rn(v.z), h3 = __float2bfloat16_rn(v.w);
            __nv_bfloat16 l0 = __float2bfloat16_rn(v.x - __bfloat162float(h0));
            __nv_bfloat16 l1 = __float2bfloat16_rn(v.y - __bfloat162float(h1));
            __nv_bfloat16 l2 = __float2bfloat16_rn(v.z - __bfloat162float(h2));
            __nv_bfloat16 l3 = __float2bfloat16_rn(v.w - __bfloat162float(h3));
            uint32_t hA = (uint32_t)__bfloat16_as_ushort(h0) |
                          ((uint32_t)__bfloat16_as_ushort(h1) << 16);
            uint32_t hB = (uint32_t)__bfloat16_as_ushort(h2) |
                          ((uint32_t)__bfloat16_as_ushort(h3) << 16);
            uint32_t lA = (uint32_t)__bfloat16_as_ushort(l0) |
                          ((uint32_t)__bfloat16_as_ushort(l1) << 16);
            uint32_t lB = (uint32_t)__bfloat16_as_ushort(l2) |
                          ((uint32_t)__bfloat16_as_ushort(l3) << 16);
            *(uint2*)(smem + G_BHI + (size_t)(r * GP + c4) * 2) = make_uint2(hA, hB);
            *(uint2*)(smem + G_BLO + (size_t)(r * GP + c4) * 2) = make_uint2(lA, lB);
        }
        __syncthreads();

        uint32_t aoff = ((uint32_t)(wm * 32 + (lane & 15)) * GP + ((lane >> 1) & 8)) * 2;
        uint32_t boff = ((uint32_t)(lane & 15) * GP + wn * 64 + ((lane >> 1) & 8)) * 2;
#pragma unroll
        for (int kk = 0; kk < 8; kk++) {
            uint32_t ahi[2][4], alo[2][4];
            ldmx4(ahi[0], sb + G_AHI + aoff + kk * 32);
            ldmx4(ahi[1], sb + G_AHI + aoff + 16 * GP * 2 + kk * 32);
            ldmx4(alo[0], sb + G_ALO + aoff + kk * 32);
            ldmx4(alo[1], sb + G_ALO + aoff + 16 * GP * 2 + kk * 32);
#pragma unroll
            for (int p = 0; p < 4; p++) {
                uint32_t bhi[4], blo[4];
                ldmx4t(bhi, sb + G_BHI + boff + kk * 16 * GP * 2 + p * 32);
                ldmx4t(blo, sb + G_BLO + boff + kk * 16 * GP * 2 + p * 32);
#pragma unroll
                for (int mt = 0; mt < 2; mt++) {
                    mma16816(c[mt][2 * p + 0], ahi[mt], bhi[0], bhi[1]);
                    mma16816(c[mt][2 * p + 1], ahi[mt], bhi[2], bhi[3]);
                    mma16816(c[mt][2 * p + 0], ahi[mt], blo[0], blo[1]);
                    mma16816(c[mt][2 * p + 1], ahi[mt], blo[2], blo[3]);
                    mma16816(c[mt][2 * p + 0], alo[mt], bhi[0], bhi[1]);
                    mma16816(c[mt][2 * p + 1], alo[mt], bhi[2], bhi[3]);
                }
            }
        }
        __syncthreads();
    }

    // epilogue
    int r0 = m0 + wm * 32 + (lane >> 2);
    int cb = n0 + wn * 64 + 2 * (lane & 3);
#pragma unroll
    for (int mt = 0; mt < 2; mt++) {
        int row = r0 + mt * 16;
#pragma unroll
        for (int nt = 0; nt < 8; nt++) {
            int col = cb + nt * 8;
            float2 v0 = make_float2(c[mt][nt][0], c[mt][nt][1]);
            float2 v1 = make_float2(c[mt][nt][2], c[mt][nt][3]);
            if (doBiasRelu) {
                float2 b = *(const float2*)&bias[col];
                v0.x = fmaxf(v0.x + b.x, 0.0f); v0.y = fmaxf(v0.y + b.y, 0.0f);
                v1.x = fmaxf(v1.x + b.x, 0.0f); v1.y = fmaxf(v1.y + b.y, 0.0f);
            }
            *(float2*)(C + (size_t)row * N + col) = v0;
            *(float2*)(C + (size_t)(row + 8) * N + col) = v1;
        }
    }
}

// ---------------- SpMM: out = P @ T (128-wide) ----------------
// mode 0: fp32 out, no bias/relu; mode 1: fp32 out + bias + relu;
// mode 2: bf16 out (g_sb) + bias + relu.
__global__ void __launch_bounds__(256) spmm_k(const float* __restrict__ T,
                                              const float* __restrict__ bias,
                                              float* __restrict__ out,
                                              int mode) {
    int gw = (blockIdx.x * blockDim.x + threadIdx.x) >> 5;
    int lane = threadIdx.x & 31;
    if (gw >= NN) return;
    int i = gw;
    float di = g_dinv[i];
    float4 ts = ((const float4*)(T + (size_t)i * NH))[lane];
    float4 acc;
    acc.x = di * ts.x; acc.y = di * ts.y; acc.z = di * ts.z; acc.w = di * ts.w;
    int e0 = g_rowptr[i], e1 = g_rowptr[i + 1];
#pragma unroll 2
    for (int e = e0; e < e1; e++) {
        int j = g_col[e];
        float w = g_dinv[j];
        float4 tv = ((const float4*)(T + (size_t)j * NH))[lane];
        acc.x += w * tv.x; acc.y += w * tv.y; acc.z += w * tv.z; acc.w += w * tv.w;
    }
    float4 r;
    r.x = di * acc.x; r.y = di * acc.y; r.z = di * acc.z; r.w = di * acc.w;
    if (mode != 0) {
        float4 b = ((const float4*)bias)[lane];
        r.x = fmaxf(r.x + b.x, 0.0f);
        r.y = fmaxf(r.y + b.y, 0.0f);
        r.z = fmaxf(r.z + b.z, 0.0f);
        r.w = fmaxf(r.w + b.w, 0.0f);
    }
    if (mode == 2) {
        uint32_t p0 = (uint32_t)__bfloat16_as_ushort(__float2bfloat16(r.x)) |
                      ((uint32_t)__bfloat16_as_ushort(__float2bfloat16(r.y)) << 16);
        uint32_t p1 = (uint32_t)__bfloat16_as_ushort(__float2bfloat16(r.z)) |
                      ((uint32_t)__bfloat16_as_ushort(__float2bfloat16(r.w)) << 16);
        *(uint2*)(g_sb + (size_t)i * NH + lane * 4) = make_uint2(p0, p1);
    } else {
        ((float4*)(out + (size_t)i * NH))[lane] = r;
    }
}

// ---------------- A_hat = S @ S^T: K-split fill, 64x64 warp tiles, STG.128.cs -------
// CTA tile 128(M) x 256(N), K=128 as two 64-wide cp.async halves. 256 thr = 8 warps
// in 2m x 4n grid, warp tile 64x64. B rows PERMUTED in smem so each thread's
// accumulators from an mma tile-pair cover 4 consecutive output columns -> float4
// streaming stores (.cs: write-once output, evict-first).
#define HPAD 72
#define HROW (HPAD * 2)              // 144 B per half-row
#define AH_A0 0
#define AH_B0 (128 * HROW)           // 18432
#define AH_A1 (AH_B0 + 256 * HROW)   // 55296
#define AH_B1 (AH_A1 + 128 * HROW)   // 73728
#define AH_SMEM (AH_B1 + 256 * HROW) // 110592

__device__ __forceinline__ int bperm(int n) {
    int t = n >> 4, w = n & 15;
    int q = w >> 2, rem = w & 3;
    int sub = rem >> 1, par = rem & 1;
    return (((t << 1) + sub) << 3) + (q << 1) + par;
}

__device__ __forceinline__ void ahat_fill_half(uint32_t base, const __nv_bfloat16* S,
                                               int m0, int n0, int h, int tid,
                                               uint32_t aoff, uint32_t boff) {
    int hc = h * 64;
#pragma unroll
    for (int i = 0; i < 4; i++) {            // A half: 1024 16B chunks / 256 thr
        int idx = tid + i * 256;
        int r = idx >> 3, c8 = (idx & 7) << 3;
        cpa16(base + aoff + (uint32_t)(r * HROW + c8 * 2),
              S + (size_t)(m0 + r) * NH + hc + c8);
    }
#pragma unroll
    for (int i = 0; i < 8; i++) {            // B half: 2048 16B chunks, permuted rows
        int idx = tid + i * 256;
        int n = idx >> 3, c8 = (idx & 7) << 3;
        int slot = bperm(n);
        cpa16(base + boff + (uint32_t)(slot * HROW + c8 * 2),
              S + (size_t)(n0 + n) * NH + hc + c8);
    }
}

__global__ void __launch_bounds__(256, 1) ahat_k(const __nv_bfloat16* __restrict__ S,
                                                 float* __restrict__ out) {
    extern __shared__ char smem[];
    uint32_t sb = smem_u32(smem);
    int tid = threadIdx.x, lane = tid & 31, wid = tid >> 5;
    int wm = wid & 1, wn = wid >> 1;         // 2m x 4n warp grid, warp tile 64x64

    int m0 = (blockIdx.x >> 6) * 128;
    int n0 = (blockIdx.x & 63) * 256;

    // issue both half-fills immediately
    ahat_fill_half(sb, S, m0, n0, 0, tid, AH_A0, AH_B0);
    cpa_commit();
    ahat_fill_half(sb, S, m0, n0, 1, tid, AH_A1, AH_B1);
    cpa_commit();

    float c[4][8][4];
#pragma unroll
    for (int mt = 0; mt < 4; mt++)
#pragma unroll
        for (int nt = 0; nt < 8; nt++)
#pragma unroll
            for (int q = 0; q < 4; q++) c[mt][nt][q] = 0.0f;

    uint32_t arow = (uint32_t)(wm * 64 + (lane & 15)) * HROW + ((lane >> 1) & 8) * 2;
    uint32_t brow = (uint32_t)(wn * 64 + (lane & 7) + ((lane >> 4) << 3)) * HROW +
                    (lane & 8) * 2;

#pragma unroll
    for (int h = 0; h < 2; h++) {
        if (h == 0) cpa_wait<1>(); else cpa_wait<0>();
        __syncthreads();
        uint32_t aAddr = sb + (h ? AH_A1 : AH_A0) + arow;
        uint32_t bAddr = sb + (h ? AH_B1 : AH_B0) + brow;
#pragma unroll
        for (int k = 0; k < 4; k++) {        // 4 k-steps of 16 per half
            uint32_t a[4][4];
#pragma unroll
            for (int mt = 0; mt < 4; mt++)
                ldmx4(a[mt], aAddr + mt * 16 * HROW + k * 32);
            uint32_t b[4][4];
#pragma unroll
            for (int p = 0; p < 4; p++)
                ldmx4(b[p], bAddr + p * 16 * HROW + k * 32);
#pragma unroll
            for (int mt = 0; mt < 4; mt++)
#pragma unroll
                for (int p = 0; p < 4; p++) {
                    mma16816(c[mt][2 * p + 0], a[mt], b[p][0], b[p][1]);
                    mma16816(c[mt][2 * p + 1], a[mt], b[p][2], b[p][3]);
                }
        }
    }

    // STG.128.cs epilogue: tile-pair (2p, 2p+1) holds interleaved actual columns so
    // thread q owns actual cols 16p + 4q .. 4q+3 contiguously.
    int r0 = m0 + wm * 64 + (lane >> 2);
    int q4 = 4 * (lane & 3);
#pragma unroll
    for (int mt = 0; mt < 4; mt++) {
        int row = r0 + mt * 16;
#pragma unroll
        for (int p = 0; p < 4; p++) {
            int col = n0 + wn * 64 + 16 * p + q4;
            stg128_cs(out + (size_t)row * NN + col,
                      c[mt][2 * p][0], c[mt][2 * p][1],
                      c[mt][2 * p + 1][0], c[mt][2 * p + 1][1]);
            stg128_cs(out + (size_t)(row + 8) * NN + col,
                      c[mt][2 * p][2], c[mt][2 * p][3],
                      c[mt][2 * p + 1][2], c[mt][2 * p + 1][3]);
        }
    }
}

// ---------------- launch ----------------
extern "C" void kernel_launch(void* const* d_in, const int* in_sizes, int n_in,
                              void* d_out, int out_size) {
    const float* x   = (const float*)d_in[0];
    const int*   ei  = (const int*)d_in[1];
    const float* We1 = (const float*)d_in[2];
    const float* be1 = (const float*)d_in[3];
    const float* We2 = (const float*)d_in[4];
    const float* be2 = (const float*)d_in[5];
    const float* Wa1 = (const float*)d_in[6];
    const float* ba1 = (const float*)d_in[7];
    const float* Wa2 = (const float*)d_in[8];
    const float* ba2 = (const float*)d_in[9];
    const float* Ws1 = (const float*)d_in[10];
    const float* bs1 = (const float*)d_in[11];

    float* Ahat = (float*)d_out;
    float* Xhat = (float*)d_out + (size_t)NN * NN;

    float *t, *b1, *b2;
    __nv_bfloat16* sb;
    cudaGetSymbolAddress((void**)&t,  g_t);
    cudaGetSymbolAddress((void**)&b1, g_b1);
    cudaGetSymbolAddress((void**)&b2, g_b2);
    cudaGetSymbolAddress((void**)&sb, g_sb);

    cudaFuncSetAttribute(gemm3bf_k, cudaFuncAttributeMaxDynamicSharedMemorySize, G_SMEM);
    cudaFuncSetAttribute(ahat_k, cudaFuncAttributeMaxDynamicSharedMemorySize, AH_SMEM);

    // ---- CSR preprocessing; PROFILING PROBE at launch slot 4 (ncu capture slot):
    // a one-wave ahat_k on g_sb (dummy data; its output region is fully overwritten
    // by the real full-grid ahat_k at the end -> correctness unaffected).
    detect_k<<<1, 128>>>(ei);                                    // 1
    zero_k<<<64, 256>>>();                                       // 2
    degree_k<<<EE / 256, 256>>>(ei);                             // 3
    ahat_k<<<148, 256, AH_SMEM>>>(sb, Ahat);                     // 4  <- profiled
    dinv_k<<<64, 256>>>();                                       // 5
    scan_k<<<1, 1024>>>();                                       // 6
    copycur_k<<<64, 256>>>();                                    // 7
    scatter_k<<<EE / 256, 256>>>(ei);                            // 8

    // ---- encoder ----
    gemm3bf_k<<<dim3(128, 1), 256, G_SMEM>>>(x, We1, nullptr, t, NN, NF, NH, 0);
    spmm_k<<<2048, 256>>>(t, be1, b1, 1);                        // z1
    gemm3bf_k<<<dim3(128, 1), 256, G_SMEM>>>(b1, We2, nullptr, t, NN, NH, NH, 0);
    spmm_k<<<2048, 256>>>(t, be2, b2, 1);                        // z2 (kept)

    // ---- attribute decoder ----
    gemm3bf_k<<<dim3(128, 1), 256, G_SMEM>>>(b2, Wa1, nullptr, t, NN, NH, NH, 0);
    spmm_k<<<2048, 256>>>(t, ba1, b1, 1);                        // a
    spmm_k<<<2048, 256>>>(b1, nullptr, t, 0);                    // u = P @ a
    gemm3bf_k<<<dim3(128, 2), 256, G_SMEM>>>(t, Wa2, ba2, Xhat, NN, NH, NF, 1); // X_hat

    // ---- structure decoder ----
    gemm3bf_k<<<dim3(128, 1), 256, G_SMEM>>>(b2, Ws1, nullptr, t, NN, NH, NH, 0);
    spmm_k<<<2048, 256>>>(t, bs1, nullptr, 2);                   // s -> g_sb (bf16)

    ahat_k<<<128 * 64, 256, AH_SMEM>>>(sb, Ahat);
}

// round 16
// speedup vs baseline: 1.0471x; 1.0471x over previous
#include <cuda_runtime.h>
#include <cuda_bf16.h>
#include <cstdint>
#include <cstddef>

#define NN 16384
#define EE 524288
#define NF 256
#define NH 128

// ---------------- scratch (static device globals; no runtime alloc) ----------------
__device__ float g_t [NN * NH];
__device__ float g_b1[NN * NH];
__device__ float g_b2[NN * NH];
__device__ __nv_bfloat16 g_sb[NN * NH];
__device__ int   g_deg[NN];
__device__ int   g_rowptr[NN + 1];
__device__ int   g_cursor[NN];
__device__ int   g_col[EE];
__device__ float g_dinv[NN];
__device__ int   g_idx64;

// ---------------- helpers ----------------
__device__ __forceinline__ uint32_t smem_u32(const void* p) {
    uint32_t a;
    asm("{ .reg .u64 t; cvta.to.shared.u64 t, %1; cvt.u32.u64 %0, t; }" : "=r"(a) : "l"(p));
    return a;
}
__device__ __forceinline__ void ldmx4(uint32_t* r, uint32_t addr) {
    asm volatile("ldmatrix.sync.aligned.m8n8.x4.shared.b16 {%0,%1,%2,%3}, [%4];"
                 : "=r"(r[0]), "=r"(r[1]), "=r"(r[2]), "=r"(r[3]) : "r"(addr));
}
__device__ __forceinline__ void ldmx4t(uint32_t* r, uint32_t addr) {
    asm volatile("ldmatrix.sync.aligned.m8n8.x4.trans.shared.b16 {%0,%1,%2,%3}, [%4];"
                 : "=r"(r[0]), "=r"(r[1]), "=r"(r[2]), "=r"(r[3]) : "r"(addr));
}
__device__ __forceinline__ void mma16816(float* c, const uint32_t* a,
                                         uint32_t b0, uint32_t b1) {
    asm volatile(
        "mma.sync.aligned.m16n8k16.row.col.f32.bf16.bf16.f32 "
        "{%0,%1,%2,%3}, {%4,%5,%6,%7}, {%8,%9}, {%0,%1,%2,%3};"
        : "+f"(c[0]), "+f"(c[1]), "+f"(c[2]), "+f"(c[3])
        : "r"(a[0]), "r"(a[1]), "r"(a[2]), "r"(a[3]), "r"(b0), "r"(b1));
}
__device__ __forceinline__ void cpa16(uint32_t dst, const void* src) {
    asm volatile("cp.async.cg.shared.global [%0], [%1], 16;" :: "r"(dst), "l"(src));
}
__device__ __forceinline__ void cpa_commit() {
    asm volatile("cp.async.commit_group;" ::: "memory");
}
template <int NPEND>
__device__ __forceinline__ void cpa_wait() {
    asm volatile("cp.async.wait_group %0;" :: "n"(NPEND) : "memory");
}
__device__ __forceinline__ void stg128_cs(float* p, float x, float y, float z, float w) {
    asm volatile("st.global.cs.v4.f32 [%0], {%1,%2,%3,%4};"
                 :: "l"(p), "f"(x), "f"(y), "f"(z), "f"(w) : "memory");
}

// ---------------- preprocessing kernels ----------------
__global__ void detect_k(const int* __restrict__ ei) {
    int t = threadIdx.x;                 // 128 threads
    int v = ei[2 * t + 1];               // high word if int64 layout
    int ok = __syncthreads_and(v == 0);
    if (t == 0) g_idx64 = ok ? 1 : 0;
}
__global__ void zero_k() {
    int i = blockIdx.x * blockDim.x + threadIdx.x;
    if (i < NN) g_deg[i] = 0;
}
__global__ void degree_k(const int* __restrict__ ei) {
    int e = blockIdx.x * blockDim.x + threadIdx.x;
    if (e >= EE) return;
    int d = g_idx64 ? ei[2 * (EE + e)] : ei[EE + e];
    atomicAdd(&g_deg[d], 1);
}
__global__ void dinv_k() {
    int i = blockIdx.x * blockDim.x + threadIdx.x;
    if (i < NN) g_dinv[i] = rsqrtf((float)g_deg[i] + 1.0f);
}
__global__ void scan_k() {
    __shared__ int sums[1024];
    int t = threadIdx.x;
    int base = t * 16;
    int local[16];
    int s = 0;
#pragma unroll
    for (int i = 0; i < 16; i++) { local[i] = s; s += g_deg[base + i]; }
    sums[t] = s;
    __syncthreads();
    for (int off = 1; off < 1024; off <<= 1) {
        int v = (t >= off) ? sums[t - off] : 0;
        __syncthreads();
        sums[t] += v;
        __syncthreads();
    }
    int pre = (t > 0) ? sums[t - 1] : 0;
#pragma unroll
    for (int i = 0; i < 16; i++) g_rowptr[base + i] = pre + local[i];
    if (t == 1023) g_rowptr[NN] = sums[1023];
}
__global__ void copycur_k() {
    int i = blockIdx.x * blockDim.x + threadIdx.x;
    if (i < NN) g_cursor[i] = g_rowptr[i];
}
__global__ void scatter_k(const int* __restrict__ ei) {
    int e = blockIdx.x * blockDim.x + threadIdx.x;
    if (e >= EE) return;
    int s, d;
    if (g_idx64) { s = ei[2 * e]; d = ei[2 * (EE + e)]; }
    else         { s = ei[e];     d = ei[EE + e]; }
    int p = atomicAdd(&g_cursor[d], 1);
    g_col[p] = s;
}

// ---------------- 3xbf16-split tensor GEMM: C[M,N] = A[M,K] @ B[K,N] (+bias, relu) ----
#define GP 136
#define G_AHI 0
#define G_ALO (128 * GP * 2)
#define G_BHI (2 * 128 * GP * 2)
#define G_BLO (3 * 128 * GP * 2)
#define G_SMEM (4 * 128 * GP * 2)

__global__ void __launch_bounds__(256) gemm3bf_k(const float* __restrict__ A,
                                                 const float* __restrict__ B,
                                                 const float* __restrict__ bias,
                                                 float* __restrict__ C,
                                                 int M, int K, int N, int doBiasRelu) {
    extern __shared__ char smem[];
    uint32_t sb = smem_u32(smem);
    int tid = threadIdx.x, lane = tid & 31, wid = tid >> 5;
    int wm = wid & 3, wn = wid >> 2;
    int m0 = blockIdx.x * 128, n0 = blockIdx.y * 128;

    float c[2][8][4];
#pragma unroll
    for (int mt = 0; mt < 2; mt++)
#pragma unroll
        for (int nt = 0; nt < 8; nt++)
#pragma unroll
            for (int q = 0; q < 4; q++) c[mt][nt][q] = 0.0f;

    for (int k0 = 0; k0 < K; k0 += 128) {
#pragma unroll
        for (int i = 0; i < 16; i++) {
            int idx = tid + i * 256;
            int r = idx >> 5, c4 = (idx & 31) << 2;
            float4 v = *(const float4*)(A + (size_t)(m0 + r) * K + k0 + c4);
            __nv_bfloat16 h0 = __float2bfloat16_rn(v.x), h1 = __float2bfloat16_rn(v.y);
            __nv_bfloat16 h2 = __float2bfloat16_rn(v.z), h3 = __float2bfloat16_rn(v.w);
            __nv_bfloat16 l0 = __float2bfloat16_rn(v.x - __bfloat162float(h0));
            __nv_bfloat16 l1 = __float2bfloat16_rn(v.y - __bfloat162float(h1));
            __nv_bfloat16 l2 = __float2bfloat16_rn(v.z - __bfloat162float(h2));
            __nv_bfloat16 l3 = __float2bfloat16_rn(v.w - __bfloat162float(h3));
            uint32_t hA = (uint32_t)__bfloat16_as_ushort(h0) |
                          ((uint32_t)__bfloat16_as_ushort(h1) << 16);
            uint32_t hB = (uint32_t)__bfloat16_as_ushort(h2) |
                          ((uint32_t)__bfloat16_as_ushort(h3) << 16);
            uint32_t lA = (uint32_t)__bfloat16_as_ushort(l0) |
                          ((uint32_t)__bfloat16_as_ushort(l1) << 16);
            uint32_t lB = (uint32_t)__bfloat16_as_ushort(l2) |
                          ((uint32_t)__bfloat16_as_ushort(l3) << 16);
            *(uint2*)(smem + G_AHI + (size_t)(r * GP + c4) * 2) = make_uint2(hA, hB);
            *(uint2*)(smem + G_ALO + (size_t)(r * GP + c4) * 2) = make_uint2(lA, lB);
        }
#pragma unroll
        for (int i = 0; i < 16; i++) {
            int idx = tid + i * 256;
            int r = idx >> 5, c4 = (idx & 31) << 2;
            float4 v = *(const float4*)(B + (size_t)(k0 + r) * N + n0 + c4);
            __nv_bfloat16 h0 = __float2bfloat16_rn(v.x), h1 = __float2bfloat16_rn(v.y);
            __nv_bfloat16 h2 = __float2bfloat16_rn(v.z), h3 = __float2bfloat16_rn(v.w);
            __nv_bfloat16 l0 = __float2bfloat16_rn(v.x - __bfloat162float(h0));
            __nv_bfloat16 l1 = __float2bfloat16_rn(v.y - __bfloat162float(h1));
            __nv_bfloat16 l2 = __float2bfloat16_rn(v.z - __bfloat162float(h2));
            __nv_bfloat16 l3 = __float2bfloat16_rn(v.w - __bfloat162float(h3));
            uint32_t hA = (uint32_t)__bfloat16_as_ushort(h0) |
                          ((uint32_t)__bfloat16_as_ushort(h1) << 16);
            uint32_t hB = (uint32_t)__bfloat16_as_ushort(h2) |
                          ((uint32_t)__bfloat16_as_ushort(h3) << 16);
            uint32_t lA = (uint32_t)__bfloat16_as_ushort(l0) |
                          ((uint32_t)__bfloat16_as_ushort(l1) << 16);
            uint32_t lB = (uint32_t)__bfloat16_as_ushort(l2) |
                          ((uint32_t)__bfloat16_as_ushort(l3) << 16);
            *(uint2*)(smem + G_BHI + (size_t)(r * GP + c4) * 2) = make_uint2(hA, hB);
            *(uint2*)(smem + G_BLO + (size_t)(r * GP + c4) * 2) = make_uint2(lA, lB);
        }
        __syncthreads();

        uint32_t aoff = ((uint32_t)(wm * 32 + (lane & 15)) * GP + ((lane >> 1) & 8)) * 2;
        uint32_t boff = ((uint32_t)(lane & 15) * GP + wn * 64 + ((lane >> 1) & 8)) * 2;
#pragma unroll
        for (int kk = 0; kk < 8; kk++) {
            uint32_t ahi[2][4], alo[2][4];
            ldmx4(ahi[0], sb + G_AHI + aoff + kk * 32);
            ldmx4(ahi[1], sb + G_AHI + aoff + 16 * GP * 2 + kk * 32);
            ldmx4(alo[0], sb + G_ALO + aoff + kk * 32);
            ldmx4(alo[1], sb + G_ALO + aoff + 16 * GP * 2 + kk * 32);
#pragma unroll
            for (int p = 0; p < 4; p++) {
                uint32_t bhi[4], blo[4];
                ldmx4t(bhi, sb + G_BHI + boff + kk * 16 * GP * 2 + p * 32);
                ldmx4t(blo, sb + G_BLO + boff + kk * 16 * GP * 2 + p * 32);
#pragma unroll
                for (int mt = 0; mt < 2; mt++) {
                    mma16816(c[mt][2 * p + 0], ahi[mt], bhi[0], bhi[1]);
                    mma16816(c[mt][2 * p + 1], ahi[mt], bhi[2], bhi[3]);
                    mma16816(c[mt][2 * p + 0], ahi[mt], blo[0], blo[1]);
                    mma16816(c[mt][2 * p + 1], ahi[mt], blo[2], blo[3]);
                    mma16816(c[mt][2 * p + 0], alo[mt], bhi[0], bhi[1]);
                    mma16816(c[mt][2 * p + 1], alo[mt], bhi[2], bhi[3]);
                }
            }
        }
        __syncthreads();
    }

    // epilogue
    int r0 = m0 + wm * 32 + (lane >> 2);
    int cb = n0 + wn * 64 + 2 * (lane & 3);
#pragma unroll
    for (int mt = 0; mt < 2; mt++) {
        int row = r0 + mt * 16;
#pragma unroll
        for (int nt = 0; nt < 8; nt++) {
            int col = cb + nt * 8;
            float2 v0 = make_float2(c[mt][nt][0], c[mt][nt][1]);
            float2 v1 = make_float2(c[mt][nt][2], c[mt][nt][3]);
            if (doBiasRelu) {
                float2 b = *(const float2*)&bias[col];
                v0.x = fmaxf(v0.x + b.x, 0.0f); v0.y = fmaxf(v0.y + b.y, 0.0f);
                v1.x = fmaxf(v1.x + b.x, 0.0f); v1.y = fmaxf(v1.y + b.y, 0.0f);
            }
            *(float2*)(C + (size_t)row * N + col) = v0;
            *(float2*)(C + (size_t)(row + 8) * N + col) = v1;
        }
    }
}

// ---------------- SpMM: out = P @ T (128-wide) ----------------
// mode 0: fp32 out, no bias/relu; mode 1: fp32 out + bias + relu;
// mode 2: bf16 out (g_sb) + bias + relu.
__global__ void __launch_bounds__(256) spmm_k(const float* __restrict__ T,
                                              const float* __restrict__ bias,
                                              float* __restrict__ out,
                                              int mode) {
    int gw = (blockIdx.x * blockDim.x + threadIdx.x) >> 5;
    int lane = threadIdx.x & 31;
    if (gw >= NN) return;
    int i = gw;
    float di = g_dinv[i];
    float4 ts = ((const float4*)(T + (size_t)i * NH))[lane];
    float4 acc;
    acc.x = di * ts.x; acc.y = di * ts.y; acc.z = di * ts.z; acc.w = di * ts.w;
    int e0 = g_rowptr[i], e1 = g_rowptr[i + 1];
#pragma unroll 2
    for (int e = e0; e < e1; e++) {
        int j = g_col[e];
        float w = g_dinv[j];
        float4 tv = ((const float4*)(T + (size_t)j * NH))[lane];
        acc.x += w * tv.x; acc.y += w * tv.y; acc.z += w * tv.z; acc.w += w * tv.w;
    }
    float4 r;
    r.x = di * acc.x; r.y = di * acc.y; r.z = di * acc.z; r.w = di * acc.w;
    if (mode != 0) {
        float4 b = ((const float4*)bias)[lane];
        r.x = fmaxf(r.x + b.x, 0.0f);
        r.y = fmaxf(r.y + b.y, 0.0f);
        r.z = fmaxf(r.z + b.z, 0.0f);
        r.w = fmaxf(r.w + b.w, 0.0f);
    }
    if (mode == 2) {
        uint32_t p0 = (uint32_t)__bfloat16_as_ushort(__float2bfloat16(r.x)) |
                      ((uint32_t)__bfloat16_as_ushort(__float2bfloat16(r.y)) << 16);
        uint32_t p1 = (uint32_t)__bfloat16_as_ushort(__float2bfloat16(r.z)) |
                      ((uint32_t)__bfloat16_as_ushort(__float2bfloat16(r.w)) << 16);
        *(uint2*)(g_sb + (size_t)i * NH + lane * 4) = make_uint2(p0, p1);
    } else {
        ((float4*)(out + (size_t)i * NH))[lane] = r;
    }
}

// ---------------- A_hat = S @ S^T: 128x128 tiles, 2 CTAs/SM, STG.128.cs -------------
// CTA tile 128(M) x 128(N), K=128 as two 64-wide cp.async halves. 256 thr = 8 warps
// in 2m x 4n grid, warp tile 64x32 (64 accum regs/thread -> fits 2 CTAs/SM in the
// 64K-reg RF; smem 72KB/CTA -> 2 CTAs fit). Cross-CTA overlap hides the serial
// fill->MMA->store chain (probe showed issue=9.4%, tensor=19.4% at 1 CTA/SM).
// B rows PERMUTED (bperm) so thread accumulators cover 4 consecutive cols -> STG.128.
#define HPAD 72
#define HROW (HPAD * 2)              // 144 B per half-row
#define AH_A0 0
#define AH_B0 (128 * HROW)           // 18432
#define AH_A1 (2 * 128 * HROW)       // 36864
#define AH_B1 (3 * 128 * HROW)       // 55296
#define AH_SMEM (4 * 128 * HROW)     // 73728

__device__ __forceinline__ int bperm(int n) {
    int t = n >> 4, w = n & 15;
    int q = w >> 2, rem = w & 3;
    int sub = rem >> 1, par = rem & 1;
    return (((t << 1) + sub) << 3) + (q << 1) + par;
}

__device__ __forceinline__ void ahat_fill_half(uint32_t base, const __nv_bfloat16* S,
                                               int m0, int n0, int h, int tid,
                                               uint32_t aoff, uint32_t boff) {
    int hc = h * 64;
#pragma unroll
    for (int i = 0; i < 4; i++) {            // A half: 1024 16B chunks / 256 thr
        int idx = tid + i * 256;
        int r = idx >> 3, c8 = (idx & 7) << 3;
        cpa16(base + aoff + (uint32_t)(r * HROW + c8 * 2),
              S + (size_t)(m0 + r) * NH + hc + c8);
    }
#pragma unroll
    for (int i = 0; i < 4; i++) {            // B half: 1024 16B chunks, permuted rows
        int idx = tid + i * 256;
        int n = idx >> 3, c8 = (idx & 7) << 3;
        int slot = bperm(n);
        cpa16(base + boff + (uint32_t)(slot * HROW + c8 * 2),
              S + (size_t)(n0 + n) * NH + hc + c8);
    }
}

__global__ void __launch_bounds__(256, 2) ahat_k(const __nv_bfloat16* __restrict__ S,
                                                 float* __restrict__ out) {
    extern __shared__ char smem[];
    uint32_t sb = smem_u32(smem);
    int tid = threadIdx.x, lane = tid & 31, wid = tid >> 5;
    int wm = wid & 1, wn = wid >> 1;         // 2m x 4n warp grid, warp tile 64x32

    int m0 = (blockIdx.x >> 7) << 7;
    int n0 = (blockIdx.x & 127) << 7;

    // issue both half-fills immediately
    ahat_fill_half(sb, S, m0, n0, 0, tid, AH_A0, AH_B0);
    cpa_commit();
    ahat_fill_half(sb, S, m0, n0, 1, tid, AH_A1, AH_B1);
    cpa_commit();

    float c[4][4][4];
#pragma unroll
    for (int mt = 0; mt < 4; mt++)
#pragma unroll
        for (int nt = 0; nt < 4; nt++)
#pragma unroll
            for (int q = 0; q < 4; q++) c[mt][nt][q] = 0.0f;

    uint32_t arow = (uint32_t)(wm * 64 + (lane & 15)) * HROW + ((lane >> 1) & 8) * 2;
    uint32_t brow = (uint32_t)(wn * 32 + (lane & 7) + ((lane >> 4) << 3)) * HROW +
                    (lane & 8) * 2;

#pragma unroll
    for (int h = 0; h < 2; h++) {
        if (h == 0) cpa_wait<1>(); else cpa_wait<0>();
        __syncthreads();
        uint32_t aAddr = sb + (h ? AH_A1 : AH_A0) + arow;
        uint32_t bAddr = sb + (h ? AH_B1 : AH_B0) + brow;
#pragma unroll
        for (int k = 0; k < 4; k++) {        // 4 k-steps of 16 per half
            uint32_t a[4][4];
#pragma unroll
            for (int mt = 0; mt < 4; mt++)
                ldmx4(a[mt], aAddr + mt * 16 * HROW + k * 32);
            uint32_t b[2][4];
#pragma unroll
            for (int p = 0; p < 2; p++)
                ldmx4(b[p], bAddr + p * 16 * HROW + k * 32);
#pragma unroll
            for (int mt = 0; mt < 4; mt++)
#pragma unroll
                for (int p = 0; p < 2; p++) {
                    mma16816(c[mt][2 * p + 0], a[mt], b[p][0], b[p][1]);
                    mma16816(c[mt][2 * p + 1], a[mt], b[p][2], b[p][3]);
                }
        }
    }

    // STG.128.cs epilogue: tile-pair (2p, 2p+1) holds interleaved actual columns so
    // thread q owns actual cols 16p + 4q .. 4q+3 contiguously.
    int r0 = m0 + wm * 64 + (lane >> 2);
    int q4 = 4 * (lane & 3);
#pragma unroll
    for (int mt = 0; mt < 4; mt++) {
        int row = r0 + mt * 16;
#pragma unroll
        for (int p = 0; p < 2; p++) {
            int col = n0 + wn * 32 + 16 * p + q4;
            stg128_cs(out + (size_t)row * NN + col,
                      c[mt][2 * p][0], c[mt][2 * p][1],
                      c[mt][2 * p + 1][0], c[mt][2 * p + 1][1]);
            stg128_cs(out + (size_t)(row + 8) * NN + col,
                      c[mt][2 * p][2], c[mt][2 * p][3],
                      c[mt][2 * p + 1][2], c[mt][2 * p + 1][3]);
        }
    }
}

// ---------------- launch ----------------
extern "C" void kernel_launch(void* const* d_in, const int* in_sizes, int n_in,
                              void* d_out, int out_size) {
    const float* x   = (const float*)d_in[0];
    const int*   ei  = (const int*)d_in[1];
    const float* We1 = (const float*)d_in[2];
    const float* be1 = (const float*)d_in[3];
    const float* We2 = (const float*)d_in[4];
    const float* be2 = (const float*)d_in[5];
    const float* Wa1 = (const float*)d_in[6];
    const float* ba1 = (const float*)d_in[7];
    const float* Wa2 = (const float*)d_in[8];
    const float* ba2 = (const float*)d_in[9];
    const float* Ws1 = (const float*)d_in[10];
    const float* bs1 = (const float*)d_in[11];

    float* Ahat = (float*)d_out;
    float* Xhat = (float*)d_out + (size_t)NN * NN;

    float *t, *b1, *b2;
    __nv_bfloat16* sb;
    cudaGetSymbolAddress((void**)&t,  g_t);
    cudaGetSymbolAddress((void**)&b1, g_b1);
    cudaGetSymbolAddress((void**)&b2, g_b2);
    cudaGetSymbolAddress((void**)&sb, g_sb);

    cudaFuncSetAttribute(gemm3bf_k, cudaFuncAttributeMaxDynamicSharedMemorySize, G_SMEM);
    cudaFuncSetAttribute(ahat_k, cudaFuncAttributeMaxDynamicSharedMemorySize, AH_SMEM);

    // ---- CSR preprocessing; PROFILING PROBE at launch slot 4 (ncu capture slot):
    // a two-wave-resident ahat_k on g_sb (dummy data; output fully overwritten by
    // the real full-grid ahat_k at the end -> correctness unaffected).
    detect_k<<<1, 128>>>(ei);                                    // 1
    zero_k<<<64, 256>>>();                                       // 2
    degree_k<<<EE / 256, 256>>>(ei);                             // 3
    ahat_k<<<296, 256, AH_SMEM>>>(sb, Ahat);                     // 4  <- profiled
    dinv_k<<<64, 256>>>();                                       // 5
    scan_k<<<1, 1024>>>();                                       // 6
    copycur_k<<<64, 256>>>();                                    // 7
    scatter_k<<<EE / 256, 256>>>(ei);                            // 8

    // ---- encoder ----
    gemm3bf_k<<<dim3(128, 1), 256, G_SMEM>>>(x, We1, nullptr, t, NN, NF, NH, 0);
    spmm_k<<<2048, 256>>>(t, be1, b1, 1);                        // z1
    gemm3bf_k<<<dim3(128, 1), 256, G_SMEM>>>(b1, We2, nullptr, t, NN, NH, NH, 0);
    spmm_k<<<2048, 256>>>(t, be2, b2, 1);                        // z2 (kept)

    // ---- attribute decoder ----
    gemm3bf_k<<<dim3(128, 1), 256, G_SMEM>>>(b2, Wa1, nullptr, t, NN, NH, NH, 0);
    spmm_k<<<2048, 256>>>(t, ba1, b1, 1);                        // a
    spmm_k<<<2048, 256>>>(b1, nullptr, t, 0);                    // u = P @ a
    gemm3bf_k<<<dim3(128, 2), 256, G_SMEM>>>(t, Wa2, ba2, Xhat, NN, NH, NF, 1); // X_hat

    // ---- structure decoder ----
    gemm3bf_k<<<dim3(128, 1), 256, G_SMEM>>>(b2, Ws1, nullptr, t, NN, NH, NH, 0);
    spmm_k<<<2048, 256>>>(t, bs1, nullptr, 2);                   // s -> g_sb (bf16)

    ahat_k<<<128 * 128, 256, AH_SMEM>>>(sb, Ahat);
}